// round 10
// baseline (speedup 1.0000x reference)
#include <cuda_runtime.h>
#include <cuda_bf16.h>
#include <cstdint>

// WeightedSumSessEmbedding: sparse COO [16384 x 1M] @ emb[1M x 64]
// NNZ=819200, row_idx sorted. Inputs: row_idx[i32], col_idx[i32],
// data[f32], num_ids[i32 scalar], embeddings[f32 1M*64]. Output f32 [16384*64].
//
// At the random-gather DRAM roofline (~4.15 TB/s). This version trims
// constant factors: persistent grid-stride blocks (no ragged final wave),
// SMEM-staged indices (R9), vectorized red.global.add.v2.f32 flushes.

#define EMB_DIM 64
#define CHUNK 64                       // nnz per warp per tile
#define THREADS 256                    // 8 warps per block
#define WARPS_PB (THREADS / 32)
#define NNZ_PB (WARPS_PB * CHUNK)      // 512 nnz per tile
#define UNROLL 16
#define BLOCKS_RES (148 * 4)           // persistent grid: 4 blocks/SM

__device__ __forceinline__ void red_add_v2(float* p, float x, float y)
{
    asm volatile("red.global.add.v2.f32 [%0], {%1, %2};"
                 :: "l"(p), "f"(x), "f"(y) : "memory");
}

__global__ void __launch_bounds__(THREADS, 4)   // 64-reg budget: 16 gathers live
weighted_seg_sum_kernel(const int* __restrict__ row_idx,
                        const int* __restrict__ col_idx,
                        const float* __restrict__ data,
                        const float* __restrict__ emb,
                        float* __restrict__ out,
                        int nnz, int ntiles)
{
    __shared__ int   s_row[NNZ_PB];
    __shared__ int   s_col[NNZ_PB];
    __shared__ float s_w[NNZ_PB];

    const int lane = threadIdx.x & 31;
    const int wl   = threadIdx.x >> 5;

    const float2* __restrict__ emb2 = reinterpret_cast<const float2*>(emb);

    for (int tile = blockIdx.x; tile < ntiles; tile += gridDim.x) {
        const int blk_base = tile * NNZ_PB;

        __syncthreads();   // protect smem reuse across tile iterations
        // ---- cooperative index staging: 512 x 12B, fully coalesced ----
        #pragma unroll
        for (int t = threadIdx.x; t < NNZ_PB; t += THREADS) {
            const int g = blk_base + t;
            if (g < nnz) {
                s_row[t] = row_idx[g];
                s_col[t] = col_idx[g];
                s_w[t]   = data[g];
            }
        }
        __syncthreads();

        const int start = blk_base + wl * CHUNK;
        if (start >= nnz) continue;
        const int end = min(start + CHUNK, nnz);
        const int l0  = wl * CHUNK;

        float2 acc = make_float2(0.0f, 0.0f);
        int cur_row = s_row[l0];

        #define FLUSH()                                                        \
            do {                                                               \
                red_add_v2(out + (size_t)cur_row * EMB_DIM + 2 * lane,         \
                           acc.x, acc.y);                                      \
                acc.x = 0.0f; acc.y = 0.0f;                                    \
            } while (0)

        #define STEP(r, w, e)                                                  \
            do {                                                               \
                if ((r) != cur_row) { FLUSH(); cur_row = (r); }                \
                acc.x = fmaf((w), (e).x, acc.x);                               \
                acc.y = fmaf((w), (e).y, acc.y);                               \
            } while (0)

        int li = l0;
        const int lend_main = l0 + ((end - start) & ~(UNROLL - 1));
        const int lend      = l0 + (end - start);

        for (; li < lend_main; li += UNROLL) {
            const int4 c0 = *reinterpret_cast<const int4*>(s_col + li);
            const int4 c1 = *reinterpret_cast<const int4*>(s_col + li + 4);
            const int4 c2 = *reinterpret_cast<const int4*>(s_col + li + 8);
            const int4 c3 = *reinterpret_cast<const int4*>(s_col + li + 12);
            const int cols[UNROLL] = {c0.x, c0.y, c0.z, c0.w,
                                      c1.x, c1.y, c1.z, c1.w,
                                      c2.x, c2.y, c2.z, c2.w,
                                      c3.x, c3.y, c3.z, c3.w};

            // 16 independent 256B gathers in flight before any consumer.
            float2 e[UNROLL];
            #pragma unroll
            for (int j = 0; j < UNROLL; ++j)
                e[j] = __ldg(emb2 + (size_t)cols[j] * 32 + lane);

            const int4 r0 = *reinterpret_cast<const int4*>(s_row + li);
            const int4 r1 = *reinterpret_cast<const int4*>(s_row + li + 4);
            const int4 r2 = *reinterpret_cast<const int4*>(s_row + li + 8);
            const int4 r3 = *reinterpret_cast<const int4*>(s_row + li + 12);
            const float4 w0 = *reinterpret_cast<const float4*>(s_w + li);
            const float4 w1 = *reinterpret_cast<const float4*>(s_w + li + 4);
            const float4 w2 = *reinterpret_cast<const float4*>(s_w + li + 8);
            const float4 w3 = *reinterpret_cast<const float4*>(s_w + li + 12);
            const int rows[UNROLL] = {r0.x, r0.y, r0.z, r0.w,
                                      r1.x, r1.y, r1.z, r1.w,
                                      r2.x, r2.y, r2.z, r2.w,
                                      r3.x, r3.y, r3.z, r3.w};
            const float wts[UNROLL] = {w0.x, w0.y, w0.z, w0.w,
                                       w1.x, w1.y, w1.z, w1.w,
                                       w2.x, w2.y, w2.z, w2.w,
                                       w3.x, w3.y, w3.z, w3.w};

            #pragma unroll
            for (int j = 0; j < UNROLL; ++j)
                STEP(rows[j], wts[j], e[j]);
        }
        for (; li < lend; ++li) {
            const int   r = s_row[li];
            const int   c = s_col[li];
            const float w = s_w[li];
            const float2 e = __ldg(emb2 + (size_t)c * 32 + lane);
            STEP(r, w, e);
        }

        FLUSH();

        #undef STEP
        #undef FLUSH
    }
}

extern "C" void kernel_launch(void* const* d_in, const int* in_sizes, int n_in,
                              void* d_out, int out_size)
{
    const int*   row_idx = (const int*)  d_in[0];
    const int*   col_idx = (const int*)  d_in[1];
    const float* data    = (const float*)d_in[2];
    const float* emb     = (const float*)d_in[4];
    float*       out     = (float*)d_out;

    const int nnz = in_sizes[0];

    cudaMemsetAsync(out, 0, (size_t)out_size * sizeof(float));

    const int ntiles = (nnz + NNZ_PB - 1) / NNZ_PB;
    const int blocks = min(ntiles, BLOCKS_RES);
    weighted_seg_sum_kernel<<<blocks, THREADS>>>(
        row_idx, col_idx, data, emb, out, nnz, ntiles);
}

// round 11
// speedup vs baseline: 1.2568x; 1.2568x over previous
#include <cuda_runtime.h>
#include <cuda_bf16.h>
#include <cstdint>

// WeightedSumSessEmbedding: sparse COO [16384 x 1M] @ emb[1M x 64]
// NNZ=819200, row_idx sorted. Inputs: row_idx[i32], col_idx[i32],
// data[f32], num_ids[i32 scalar], embeddings[f32 1M*64]. Output f32 [16384*64].
//
// Final: R9 structure (independent blocks, SMEM-staged indices, MLP=16
// register gathers, CHUNK=64/warp) + vectorized red.global.add.v2.f32
// flushes. Measured to sit on the ~4.15 TB/s random-256B-gather roofline.

#define EMB_DIM 64
#define CHUNK 64                       // nnz per warp
#define THREADS 256                    // 8 warps per block
#define WARPS_PB (THREADS / 32)
#define NNZ_PB (WARPS_PB * CHUNK)      // 512 nnz per block
#define UNROLL 16

__device__ __forceinline__ void red_add_v2(float* p, float x, float y)
{
    asm volatile("red.global.add.v2.f32 [%0], {%1, %2};"
                 :: "l"(p), "f"(x), "f"(y) : "memory");
}

__global__ void __launch_bounds__(THREADS, 4)   // 64-reg budget: 16 gathers live
weighted_seg_sum_kernel(const int* __restrict__ row_idx,
                        const int* __restrict__ col_idx,
                        const float* __restrict__ data,
                        const float* __restrict__ emb,
                        float* __restrict__ out,
                        int nnz)
{
    __shared__ int   s_row[NNZ_PB];
    __shared__ int   s_col[NNZ_PB];
    __shared__ float s_w[NNZ_PB];

    const int lane     = threadIdx.x & 31;
    const int wl       = threadIdx.x >> 5;
    const int blk_base = blockIdx.x * NNZ_PB;

    // ---- cooperative index staging: 512 x 12B, fully coalesced ----
    #pragma unroll
    for (int t = threadIdx.x; t < NNZ_PB; t += THREADS) {
        const int g = blk_base + t;
        if (g < nnz) {
            s_row[t] = row_idx[g];
            s_col[t] = col_idx[g];
            s_w[t]   = data[g];
        }
    }
    __syncthreads();

    const int start = blk_base + wl * CHUNK;          // global
    if (start >= nnz) return;
    const int end   = min(start + CHUNK, nnz);
    const int l0    = wl * CHUNK;                     // local (smem) offset

    // Each lane owns two consecutive dims via float2: [2*lane, 2*lane+1].
    const float2* __restrict__ emb2 = reinterpret_cast<const float2*>(emb);

    float2 acc = make_float2(0.0f, 0.0f);
    int cur_row = s_row[l0];

    #define FLUSH()                                                          \
        do {                                                                 \
            red_add_v2(out + (size_t)cur_row * EMB_DIM + 2 * lane,           \
                       acc.x, acc.y);                                        \
            acc.x = 0.0f; acc.y = 0.0f;                                      \
        } while (0)

    #define STEP(r, w, e)                                                    \
        do {                                                                 \
            if ((r) != cur_row) { FLUSH(); cur_row = (r); }                  \
            acc.x = fmaf((w), (e).x, acc.x);                                 \
            acc.y = fmaf((w), (e).y, acc.y);                                 \
        } while (0)

    int li = l0;
    const int lend_main = l0 + ((end - start) & ~(UNROLL - 1));
    const int lend      = l0 + (end - start);

    for (; li < lend_main; li += UNROLL) {
        // 29-cyc broadcast LDS.128s — off the DRAM critical path.
        const int4 c0 = *reinterpret_cast<const int4*>(s_col + li);
        const int4 c1 = *reinterpret_cast<const int4*>(s_col + li + 4);
        const int4 c2 = *reinterpret_cast<const int4*>(s_col + li + 8);
        const int4 c3 = *reinterpret_cast<const int4*>(s_col + li + 12);
        const int cols[UNROLL] = {c0.x, c0.y, c0.z, c0.w,
                                  c1.x, c1.y, c1.z, c1.w,
                                  c2.x, c2.y, c2.z, c2.w,
                                  c3.x, c3.y, c3.z, c3.w};

        // 16 independent 256B gathers in flight before any consumer.
        float2 e[UNROLL];
        #pragma unroll
        for (int j = 0; j < UNROLL; ++j)
            e[j] = __ldg(emb2 + (size_t)cols[j] * 32 + lane);

        const int4 r0 = *reinterpret_cast<const int4*>(s_row + li);
        const int4 r1 = *reinterpret_cast<const int4*>(s_row + li + 4);
        const int4 r2 = *reinterpret_cast<const int4*>(s_row + li + 8);
        const int4 r3 = *reinterpret_cast<const int4*>(s_row + li + 12);
        const float4 w0 = *reinterpret_cast<const float4*>(s_w + li);
        const float4 w1 = *reinterpret_cast<const float4*>(s_w + li + 4);
        const float4 w2 = *reinterpret_cast<const float4*>(s_w + li + 8);
        const float4 w3 = *reinterpret_cast<const float4*>(s_w + li + 12);
        const int rows[UNROLL] = {r0.x, r0.y, r0.z, r0.w,
                                  r1.x, r1.y, r1.z, r1.w,
                                  r2.x, r2.y, r2.z, r2.w,
                                  r3.x, r3.y, r3.z, r3.w};
        const float wts[UNROLL] = {w0.x, w0.y, w0.z, w0.w,
                                   w1.x, w1.y, w1.z, w1.w,
                                   w2.x, w2.y, w2.z, w2.w,
                                   w3.x, w3.y, w3.z, w3.w};

        #pragma unroll
        for (int j = 0; j < UNROLL; ++j)
            STEP(rows[j], wts[j], e[j]);
    }
    // Tail (NNZ multiple of 16 in practice; kept for generality).
    for (; li < lend; ++li) {
        const int   r = s_row[li];
        const int   c = s_col[li];
        const float w = s_w[li];
        const float2 e = __ldg(emb2 + (size_t)c * 32 + lane);
        STEP(r, w, e);
    }

    FLUSH();

    #undef STEP
    #undef FLUSH
}

extern "C" void kernel_launch(void* const* d_in, const int* in_sizes, int n_in,
                              void* d_out, int out_size)
{
    const int*   row_idx = (const int*)  d_in[0];
    const int*   col_idx = (const int*)  d_in[1];
    const float* data    = (const float*)d_in[2];
    const float* emb     = (const float*)d_in[4];
    float*       out     = (float*)d_out;

    const int nnz = in_sizes[0];

    cudaMemsetAsync(out, 0, (size_t)out_size * sizeof(float));

    const int blocks = (nnz + NNZ_PB - 1) / NNZ_PB;
    weighted_seg_sum_kernel<<<blocks, THREADS>>>(
        row_idx, col_idx, data, emb, out, nnz);
}

// round 13
// speedup vs baseline: 1.5024x; 1.1954x over previous
#include <cuda_runtime.h>
#include <cuda_bf16.h>
#include <cstdint>

// WeightedSumSessEmbedding: sparse COO [16384 x 1M] @ emb[1M x 64]
// NNZ=819200, row_idx sorted. Inputs: row_idx[i32], col_idx[i32],
// data[f32], num_ids[i32 scalar], embeddings[f32 1M*64]. Output f32 [16384*64].
//
// Half-warp float4 scheme: 16 lanes cover one 256B embedding row (float4 per
// lane), so each LDG.128 gathers TWO nnz (one per half-warp). Halves gather
// instruction count, LDS index reads, and (via red.add.v4) atomic lane-ops
// vs the R11 float2 kernel, at identical DRAM bytes and in-flight nnz.

#define EMB_DIM 64
#define CHUNK 64                       // nnz per warp
#define THREADS 256                    // 8 warps per block
#define WARPS_PB (THREADS / 32)
#define NNZ_PB (WARPS_PB * CHUNK)      // 512 nnz per block
#define PUNROLL 8                      // 8 LDG.128 per iter = 16 nnz

__device__ __forceinline__ void red_add_v4(float* p, float4 v)
{
    asm volatile("red.global.add.v4.f32 [%0], {%1, %2, %3, %4};"
                 :: "l"(p), "f"(v.x), "f"(v.y), "f"(v.z), "f"(v.w) : "memory");
}

__global__ void __launch_bounds__(THREADS, 4)   // 64-reg budget
weighted_seg_sum_kernel(const int* __restrict__ row_idx,
                        const int* __restrict__ col_idx,
                        const float* __restrict__ data,
                        const float* __restrict__ emb,
                        float* __restrict__ out,
                        int nnz)
{
    __shared__ int   s_row[NNZ_PB];
    __shared__ int   s_col[NNZ_PB];
    __shared__ float s_w[NNZ_PB];

    const int lane     = threadIdx.x & 31;
    const int half     = lane >> 4;           // which nnz of each pair
    const int sub      = lane & 15;           // float4 slot within the row
    const int wl       = threadIdx.x >> 5;
    const int blk_base = blockIdx.x * NNZ_PB;

    // ---- cooperative index staging: 512 x 12B, fully coalesced ----
    #pragma unroll
    for (int t = threadIdx.x; t < NNZ_PB; t += THREADS) {
        const int g = blk_base + t;
        if (g < nnz) {
            s_row[t] = row_idx[g];
            s_col[t] = col_idx[g];
            s_w[t]   = data[g];
        }
    }
    __syncthreads();

    const int start = blk_base + wl * CHUNK;
    if (start >= nnz) return;
    const int n  = min(CHUNK, nnz - start);
    const int l0 = wl * CHUNK;

    // emb viewed as float4: one row = 16 float4s; lane sub owns dims [4*sub..4*sub+3].
    const float4* __restrict__ emb4 = reinterpret_cast<const float4*>(emb);

    float4 acc = make_float4(0.0f, 0.0f, 0.0f, 0.0f);
    // First nnz this half touches (guard tiny chunks).
    int cur_row = s_row[l0 + min(half, n - 1)];

    #define FLUSH()                                                          \
        do {                                                                 \
            red_add_v4(out + (size_t)cur_row * EMB_DIM + 4 * sub, acc);      \
            acc.x = 0.0f; acc.y = 0.0f; acc.z = 0.0f; acc.w = 0.0f;          \
        } while (0)

    // NOTE: collision-proof macro parameter names (no bare w/e/r).
    #define STEP(_r, _w, _e)                                                 \
        do {                                                                 \
            if ((_r) != cur_row) { FLUSH(); cur_row = (_r); }                \
            acc.x = fmaf((_w), (_e).x, acc.x);                               \
            acc.y = fmaf((_w), (_e).y, acc.y);                               \
            acc.z = fmaf((_w), (_e).z, acc.z);                               \
            acc.w = fmaf((_w), (_e).w, acc.w);                               \
        } while (0)

    int li = l0;
    const int lend = l0 + n;

    // Main loop: 16 nnz per iteration via 8 LDG.128 (2 nnz per instruction).
    for (; li + 2 * PUNROLL <= lend; li += 2 * PUNROLL) {
        int cols[PUNROLL];
        #pragma unroll
        for (int j = 0; j < PUNROLL; ++j)
            cols[j] = s_col[li + 2 * j + half];       // LDS broadcast per half

        // 8 independent LDG.128s in flight before any consumer.
        float4 ev[PUNROLL];
        #pragma unroll
        for (int j = 0; j < PUNROLL; ++j)
            ev[j] = __ldg(emb4 + (size_t)cols[j] * 16 + sub);

        int   rowsv[PUNROLL];
        float wtsv[PUNROLL];
        #pragma unroll
        for (int j = 0; j < PUNROLL; ++j) {
            rowsv[j] = s_row[li + 2 * j + half];
            wtsv[j]  = s_w[li + 2 * j + half];
        }

        #pragma unroll
        for (int j = 0; j < PUNROLL; ++j)
            STEP(rowsv[j], wtsv[j], ev[j]);
    }

    // Tail: process remaining (<16) nnz in pairs; invalid half-slots are
    // neutralized (weight=0, row=cur_row) so they contribute nothing.
    for (; li < lend; li += 2) {
        const int  idx   = li + half;
        const bool valid = idx < lend;
        const int   cv = valid ? s_col[idx] : 0;
        const float wv = valid ? s_w[idx]   : 0.0f;
        const int   rv = valid ? s_row[idx] : cur_row;
        const float4 ev = __ldg(emb4 + (size_t)cv * 16 + sub);
        STEP(rv, wv, ev);
    }

    FLUSH();

    #undef STEP
    #undef FLUSH
}

extern "C" void kernel_launch(void* const* d_in, const int* in_sizes, int n_in,
                              void* d_out, int out_size)
{
    const int*   row_idx = (const int*)  d_in[0];
    const int*   col_idx = (const int*)  d_in[1];
    const float* data    = (const float*)d_in[2];
    const float* emb     = (const float*)d_in[4];
    float*       out     = (float*)d_out;

    const int nnz = in_sizes[0];

    cudaMemsetAsync(out, 0, (size_t)out_size * sizeof(float));

    const int blocks = (nnz + NNZ_PB - 1) / NNZ_PB;
    weighted_seg_sum_kernel<<<blocks, THREADS>>>(
        row_idx, col_idx, data, emb, out, nnz);
}